// round 16
// baseline (speedup 1.0000x reference)
#include <cuda_runtime.h>
#include <cuda_fp16.h>
#include <cstdint>

// ---------------- problem constants ----------------
#define NB 4
#define CDIM 384
#define CQ 192
#define IH 256
#define IW 256
#define H2 128
#define W2 128
#define NHEADS 8
#define HD 24
#define ATT_SCALE 0.2041241452319315f   // 24^-0.5

constexpr int HW  = IH * IW;   // 65536
constexpr int HW2 = H2 * W2;   // 16384

// ---------------- scratch (device globals; no runtime alloc) ----------------
__device__ uint32_t g_qwh[CQ * CDIM / 2];         // q weights, fragment-order half2
__device__ uint32_t g_pwh[CDIM * CQ / 2];         // proj weights, fragment-order half2
__device__ uint32_t g_weh[CDIM * CDIM / 2];       // kv weights (DWT-folded), fragment-order half2
__device__ uint32_t g_qfh[(size_t)NB * CQ * HW / 2];     // qfeat, half2 pixel-pairs (100MB)
__device__ uint32_t g_kvh[(size_t)NB * CDIM * HW2 / 2];  // kv, half2 token-pairs (50MB)
__device__ uint32_t g_fh[(size_t)NB * (CQ / 2) * HW];    // feat, half2 channel-pairs (100MB)

// ---------------- helpers ----------------
__device__ __forceinline__ uint32_t smem_u32(const void* p) {
    uint32_t a;
    asm("{ .reg .u64 t; cvta.to.shared.u64 t, %1; cvt.u32.u64 %0, t; }" : "=r"(a) : "l"(p));
    return a;
}
__device__ __forceinline__ void cp_async16(uint32_t dst, const void* src) {
    asm volatile("cp.async.ca.shared.global [%0], [%1], 16;"
                 :: "r"(dst), "l"(__cvta_generic_to_global(src)));
}
#define CP_COMMIT() asm volatile("cp.async.commit_group;" ::: "memory")
#define CP_WAIT0()  asm volatile("cp.async.wait_group 0;"  ::: "memory")

__device__ __forceinline__ uint32_t packh2(float lo, float hi) {
    __half2 h = __floats2half2_rn(lo, hi);
    return *reinterpret_cast<uint32_t*>(&h);
}

// m16n8k16 fp16 mma, fp32 accumulate (baseline PTX, sm_80+)
__device__ __forceinline__ void mma16(float* c, const uint32_t* a, const uint32_t* b) {
    asm volatile(
        "mma.sync.aligned.m16n8k16.row.col.f32.f16.f16.f32 "
        "{%0,%1,%2,%3}, {%4,%5,%6,%7}, {%8,%9}, {%0,%1,%2,%3};"
        : "+f"(c[0]), "+f"(c[1]), "+f"(c[2]), "+f"(c[3])
        : "r"(a[0]), "r"(a[1]), "r"(a[2]), "r"(a[3]), "r"(b[0]), "r"(b[1]));
}

// ---------------- prep: weights -> fp16 fragment order --------------------------
template<int BM, int KTOT>
__global__ void prep_arrange_h(const float* __restrict__ src, uint32_t* __restrict__ dst,
                               int mtot) {
    int idx = blockIdx.x * blockDim.x + threadIdx.x;
    if (idx >= mtot * KTOT / 2) return;
    constexpr int WPB = BM * KTOT / 2;
    constexpr int WPC = BM * 16;
    int mblk = idx / WPB;
    int r    = idx % WPB;
    int c    = r / WPC;
    int t    = r % WPC;
    int tile = t >> 7;
    int lane = (t >> 2) & 31;
    int q    = t & 3;
    int wmi = tile >> 1, ks = tile & 1;
    int row = mblk * BM + wmi * 16 + (lane >> 2) + (q & 1) * 8;
    int k   = c * 32 + ks * 16 + 2 * (lane & 3) + (q >> 1) * 8;
    const float* s = src + (size_t)row * KTOT + k;
    dst[idx] = packh2(s[0], s[1]);
}

// ---------------- prep: kv weights -> DWT-folded fp16 fragment order (fused) ----
// We[ch][c_rel*4+pos] = Haar fold of kv_w[ch][c_rel*4 + 0..3]; k always even so
// both packed elements share the same c4 quad.
__global__ void prep_arrange_kv(const float* __restrict__ kvw, uint32_t* __restrict__ dst) {
    int idx = blockIdx.x * blockDim.x + threadIdx.x;
    if (idx >= CDIM * CDIM / 2) return;
    constexpr int BM = 96, KTOT = 384;
    constexpr int WPB = BM * KTOT / 2;
    constexpr int WPC = BM * 16;
    int mblk = idx / WPB;
    int r    = idx % WPB;
    int c    = r / WPC;
    int t    = r % WPC;
    int tile = t >> 7;
    int lane = (t >> 2) & 31;
    int q    = t & 3;
    int wmi = tile >> 1, ks = tile & 1;
    int row = wmi * 16 + (lane >> 2) + (q & 1) * 8;          // 0..95 local
    int k   = c * 32 + ks * 16 + 2 * (lane & 3) + (q >> 1) * 8;  // even
    int ch  = mblk * 96 + row;
    int c4  = k & ~3;
    int pos = k & 3;                                         // 0 or 2
    const float* w = kvw + (size_t)ch * CDIM + c4;
    float a = w[0], b = w[1], cc = w[2], d = w[3];
    float v0, v1;
    if (pos == 0) { v0 = 0.5f * (a - b - cc + d); v1 = 0.5f * (a - b + cc - d); }
    else          { v0 = 0.5f * (a + b - cc - d); v1 = 0.5f * (a + b + cc + d); }
    dst[idx] = packh2(v0, v1);
}

// ---------------- fp16 mma GEMM -------------------------------------------------
// MODE 0: X fp32 [K,N] rows (register-staged B + packh2)
// MODE 1: kv fused DWT gather (register-staged)
// MODE 2: X half2 K-pair words [K/2][N] (pure cp.async B)
// OUTH: store output as half2 adjacent-n pair words (pitch N/2).
template<int WARPS_M, int KTOT, int MODE, int MTOT, bool BIAS, bool OUTH>
__global__ __launch_bounds__(256, 2) void hmma_gemm(
    const uint32_t* __restrict__ Wt, const float* __restrict__ X,
    float* __restrict__ Y, const float* __restrict__ bias, int N)
{
    constexpr int BM      = 48 * WARPS_M;
    constexpr int WARPS_N = 8 / WARPS_M;
    constexpr int WN      = 64 / WARPS_N;
    constexpr int NTW     = WN / 8;
    constexpr int MT      = 3;
    constexpr int NCH     = KTOT / 32;
    constexpr int AW      = BM * 16;
    constexpr int BW      = 16 * 72;
    constexpr int BUFW    = AW + BW;
    constexpr int ACP     = AW / 4;

    extern __shared__ __align__(16) uint32_t sw[];
    const uint32_t sbase = smem_u32(sw);
    const int tid = threadIdx.x, wid = tid >> 5, lane = tid & 31;
    const int wm = wid / WARPS_N, wn = wid % WARPS_N;
    const int g = lane >> 2, tig = lane & 3;

    const uint32_t* Wp;
    const float* Xp = nullptr;
    const uint32_t* Xw = nullptr;
    const float* bp = bias;
    size_t yoff = 0;
    int y2 = 0, xb = 0;
    const int n0 = blockIdx.x * 64;

    if (MODE == 0 || MODE == 2) {
        int b = blockIdx.z, mblk = blockIdx.y;
        Wp = Wt + (size_t)mblk * (BM * KTOT / 2);
        if (MODE == 0) Xp = X + (size_t)b * KTOT * N;
        else           Xw = (const uint32_t*)X + (size_t)b * (KTOT / 2) * N;
        yoff = ((size_t)b * MTOT + mblk * BM) * (size_t)(OUTH ? N / 2 : N);
        if (BIAS) bp = bias + mblk * BM;
    } else {
        int b = blockIdx.z >> 2, gg = blockIdx.z & 3;
        Wp = Wt + (size_t)gg * (BM * KTOT / 2);
        Xp = X + ((size_t)b * CDIM + gg * 96) * HW;
        yoff = ((size_t)b * CDIM + gg * 96) * (size_t)(OUTH ? N / 2 : N);
        y2 = n0 >> 7; xb = n0 & 127;
    }

    float acc[MT][NTW][4] = {};
    float4 bR0, bR1;
    float2 bS2[4];

    auto loadA = [&](int c, int buf) {
        const uint32_t As = sbase + (uint32_t)buf * BUFW * 4;
        const uint32_t* src = Wp + (size_t)c * AW;
        #pragma unroll
        for (int i = 0; i < (ACP + 255) / 256; i++) {
            int e = tid + i * 256;
            if (ACP % 256 == 0 || e < ACP)
                cp_async16(As + e * 16, src + e * 4);
        }
        if (MODE == 2) {
            int k2 = tid >> 4, n4 = (tid & 15) * 4;
            cp_async16(As + (AW + k2 * 72 + n4) * 4,
                       Xw + (size_t)(c * 16 + k2) * N + n0 + n4);
        }
        CP_COMMIT();
    };

    auto loadB = [&](int c) {
        const int k0 = c * 32;
        if (MODE == 0) {
            int k2 = tid >> 4, n4 = (tid & 15) * 4;
            bR0 = *(const float4*)(Xp + (size_t)(k0 + 2 * k2)     * N + n0 + n4);
            bR1 = *(const float4*)(Xp + (size_t)(k0 + 2 * k2 + 1) * N + n0 + n4);
        } else if (MODE == 1) {
            const int crel0 = c * 8;
            #pragma unroll
            for (int i = 0; i < 4; i++) {
                int e = tid + i * 256;
                int ch = e >> 7, row = (e >> 6) & 1, c2 = e & 63;
                bS2[i] = *(const float2*)(Xp + (size_t)(crel0 + ch) * HW
                                          + (2 * y2 + row) * IW + 2 * xb + 2 * c2);
            }
        }
    };

    auto storeB = [&](int buf) {
        uint32_t* Bs = sw + buf * BUFW + AW;
        if (MODE == 0) {
            int k2 = tid >> 4, n4 = (tid & 15) * 4;
            uint4 v;
            v.x = packh2(bR0.x, bR1.x);
            v.y = packh2(bR0.y, bR1.y);
            v.z = packh2(bR0.z, bR1.z);
            v.w = packh2(bR0.w, bR1.w);
            *(uint4*)(Bs + k2 * 72 + n4) = v;
        } else if (MODE == 1) {
            #pragma unroll
            for (int i = 0; i < 4; i++) {
                int e = tid + i * 256;
                int ch = e >> 7, row = (e >> 6) & 1, c2 = e & 63;
                int k2 = ch * 2 + row;
                Bs[k2 * 72 + c2] = packh2(bS2[i].x, bS2[i].y);
            }
        }
    };

    auto compute = [&](int buf) {
        const uint32_t* As = sw + buf * BUFW;
        const uint32_t* Bs = As + AW;
        #pragma unroll
        for (int ks = 0; ks < 2; ks++) {
            uint32_t a[MT][4], b[NTW][2];
            #pragma unroll
            for (int i = 0; i < MT; i++) {
                uint4 v = *(const uint4*)(As + (((wm * 3 + i) * 2 + ks) * 32 + lane) * 4);
                a[i][0] = v.x; a[i][1] = v.y; a[i][2] = v.z; a[i][3] = v.w;
            }
            #pragma unroll
            for (int j = 0; j < NTW; j++) {
                const uint32_t* p = Bs + (ks * 8 + tig) * 72 + wn * WN + j * 8 + g;
                b[j][0] = p[0];
                b[j][1] = p[4 * 72];
            }
            #pragma unroll
            for (int i = 0; i < MT; i++)
                #pragma unroll
                for (int j = 0; j < NTW; j++)
                    mma16(acc[i][j], a[i], b[j]);
        }
    };

    loadA(0, 0);
    loadB(0);
    storeB(0);
    CP_WAIT0();
    __syncthreads();
    for (int c = 0; c < NCH; c++) {
        if (c + 1 < NCH) { loadA(c + 1, (c + 1) & 1); loadB(c + 1); }
        compute(c & 1);
        if (c + 1 < NCH) {
            storeB((c + 1) & 1);
            CP_WAIT0();
            __syncthreads();
        }
    }

    // ---- epilogue ----
    const int mb = wm * 48;
    const int nb = n0 + wn * WN;
    if (OUTH) {
        uint32_t* Yh = (uint32_t*)Y + yoff;
        #pragma unroll
        for (int i = 0; i < MT; i++) {
            int r0 = mb + i * 16 + g;
            #pragma unroll
            for (int j = 0; j < NTW; j++) {
                int ncw = (nb + j * 8) / 2 + tig;
                Yh[(size_t)r0 * (N / 2) + ncw]       = packh2(acc[i][j][0], acc[i][j][1]);
                Yh[(size_t)(r0 + 8) * (N / 2) + ncw] = packh2(acc[i][j][2], acc[i][j][3]);
            }
        }
    } else {
        float* Yp = Y + yoff;
        #pragma unroll
        for (int i = 0; i < MT; i++) {
            int r0 = mb + i * 16 + g;
            float b0 = 0.f, b1 = 0.f;
            if (BIAS) { b0 = bp[r0]; b1 = bp[r0 + 8]; }
            #pragma unroll
            for (int j = 0; j < NTW; j++) {
                int nc = nb + j * 8 + tig * 2;
                *(float2*)(Yp + (size_t)r0 * N + nc) =
                    make_float2(acc[i][j][0] + b0, acc[i][j][1] + b0);
                *(float2*)(Yp + (size_t)(r0 + 8) * N + nc) =
                    make_float2(acc[i][j][2] + b1, acc[i][j][3] + b1);
            }
        }
    }
}

// ---------------- attention: bilinear, register-blocked -------------------------
// Phase 2: M = scale*K^T V, k/v unpacked fp32 in smem (from half2 token-pairs).
// Phase 3: feat = q*M, q from half2 pixel-pair words, feat written as half2
// channel-pair words (proj B layout).
constexpr int KS_F = 192 * 17;
constexpr int MS_F = 24 * 200;
constexpr int ATTN_SMEM = (2 * KS_F + MS_F) * 4;   // 45312 B

__global__ __launch_bounds__(256, 3) void attn_kernel()
{
    extern __shared__ float sm[];
    float* ks = sm;
    float* vs = ks + KS_F;
    float* Ms = vs + KS_F;

    const int w = blockIdx.x;
    const int b  = w >> 10;
    const int wl = w & 1023;
    const int wy = wl >> 5, wx = wl & 31;
    const int tid = threadIdx.x;

    const uint32_t* kvb = g_kvh + (size_t)b * CDIM * (HW2 / 2);
    #pragma unroll
    for (int i = 0; i < 3; i++) {
        int e = tid + i * 256;            // 0..767 = 192ch x 4 rows
        int ch = e >> 2, r4 = e & 3;
        int y2 = wy * 4 + r4;
        size_t woff = (size_t)ch * (HW2 / 2) + y2 * (W2 / 2) + wx * 2;
        uint2 kw = *(const uint2*)(kvb + woff);
        uint2 vw = *(const uint2*)(kvb + (size_t)CQ * (HW2 / 2) + woff);
        float2 k0 = __half22float2(*reinterpret_cast<__half2*>(&kw.x));
        float2 k1 = __half22float2(*reinterpret_cast<__half2*>(&kw.y));
        float2 v0 = __half22float2(*reinterpret_cast<__half2*>(&vw.x));
        float2 v1 = __half22float2(*reinterpret_cast<__half2*>(&vw.y));
        float* kd = ks + ch * 17 + r4 * 4;
        kd[0] = k0.x; kd[1] = k0.y; kd[2] = k1.x; kd[3] = k1.y;
        float* vd = vs + ch * 17 + r4 * 4;
        vd[0] = v0.x; vd[1] = v0.y; vd[2] = v1.x; vd[3] = v1.y;
    }
    __syncthreads();

    {
        const int h = tid >> 5, lane = tid & 31;
        const int e0 = (lane >> 2) * 3, d0 = (lane & 3) * 6;
        float acc[3][6] = {};
        const float* kp = ks + (h * 24 + e0) * 17;
        const float* vp = vs + (h * 24 + d0) * 17;
        #pragma unroll
        for (int t = 0; t < 16; t++) {
            float kk[3], vv[6];
            #pragma unroll
            for (int i = 0; i < 3; i++) kk[i] = kp[i * 17 + t];
            #pragma unroll
            for (int j = 0; j < 6; j++) vv[j] = vp[j * 17 + t];
            #pragma unroll
            for (int i = 0; i < 3; i++)
                #pragma unroll
                for (int j = 0; j < 6; j++)
                    acc[i][j] = fmaf(kk[i], vv[j], acc[i][j]);
        }
        #pragma unroll
        for (int i = 0; i < 3; i++)
            #pragma unroll
            for (int j = 0; j < 6; j++)
                Ms[(e0 + i) * 200 + h * 25 + d0 + j] = acc[i][j] * ATT_SCALE;
    }
    __syncthreads();

    {
        const int q4 = tid >> 4;
        const int h  = (tid >> 1) & 7;
        const int dh = tid & 1;
        const int p0 = q4 * 4;
        const int y = wy * 8 + (p0 >> 3), x = wx * 8 + (p0 & 7);
        float acc[4][12] = {};
        const uint32_t* qp = g_qfh + ((size_t)b * CQ + h * 24) * (HW / 2)
                             + ((y * IW + x) >> 1);
        const float* mp = Ms + h * 25 + dh * 12;
        #pragma unroll
        for (int e = 0; e < 24; e++) {
            uint2 wv = *(const uint2*)(qp + (size_t)e * (HW / 2));
            float2 f0 = __half22float2(*reinterpret_cast<__half2*>(&wv.x));
            float2 f1 = __half22float2(*reinterpret_cast<__half2*>(&wv.y));
            float q0 = f0.x, q1 = f0.y, q2 = f1.x, q3 = f1.y;
            #pragma unroll
            for (int j = 0; j < 12; j++) {
                float mv = mp[e * 200 + j];
                acc[0][j] = fmaf(q0, mv, acc[0][j]);
                acc[1][j] = fmaf(q1, mv, acc[1][j]);
                acc[2][j] = fmaf(q2, mv, acc[2][j]);
                acc[3][j] = fmaf(q3, mv, acc[3][j]);
            }
        }
        uint32_t* fb = g_fh + ((size_t)b * (CQ / 2) + (h * 24 + dh * 12) / 2) * HW
                       + y * IW + x;
        #pragma unroll
        for (int jp = 0; jp < 6; jp++) {
            uint4 wv;
            wv.x = packh2(acc[0][2 * jp], acc[0][2 * jp + 1]);
            wv.y = packh2(acc[1][2 * jp], acc[1][2 * jp + 1]);
            wv.z = packh2(acc[2][2 * jp], acc[2][2 * jp + 1]);
            wv.w = packh2(acc[3][2 * jp], acc[3][2 * jp + 1]);
            *(uint4*)(fb + (size_t)jp * HW) = wv;
        }
    }
}

// ---------------- launch ----------------
extern "C" void kernel_launch(void* const* d_in, const int* in_sizes, int n_in,
                              void* d_out, int out_size) {
    const float* x      = (const float*)d_in[0];
    const float* q_w    = (const float*)d_in[1];
    const float* kv_w   = (const float*)d_in[2];
    const float* proj_w = (const float*)d_in[3];
    const float* proj_b = (const float*)d_in[4];
    float* out = (float*)d_out;

    uint32_t *qwh, *pwh, *weh, *qfh, *kvh, *fh;
    cudaGetSymbolAddress((void**)&qwh, g_qwh);
    cudaGetSymbolAddress((void**)&pwh, g_pwh);
    cudaGetSymbolAddress((void**)&weh, g_weh);
    cudaGetSymbolAddress((void**)&qfh, g_qfh);
    cudaGetSymbolAddress((void**)&kvh, g_kvh);
    cudaGetSymbolAddress((void**)&fh, g_fh);

    auto kq = hmma_gemm<4, 384, 0, 192, false, true >;  // q -> half2 qfeat
    auto kk = hmma_gemm<2, 384, 1,  96, false, true >;  // kv -> half2 token-pairs
    auto kp = hmma_gemm<4, 192, 2, 384, true,  false>;  // proj: B = half2 feat words

    const int smem_g  = 2 * (192 * 16 + 16 * 72) * 4;  // 33792
    const int smem_kv = 2 * ( 96 * 16 + 16 * 72) * 4;  // 21504

    static bool init_done = false;
    static cudaStream_t s1;
    static cudaEvent_t evFork, evJoin;
    if (!init_done) {
        cudaFuncSetAttribute(kq, cudaFuncAttributeMaxDynamicSharedMemorySize, smem_g);
        cudaFuncSetAttribute(kk, cudaFuncAttributeMaxDynamicSharedMemorySize, smem_kv);
        cudaFuncSetAttribute(kp, cudaFuncAttributeMaxDynamicSharedMemorySize, smem_g);
        cudaFuncSetAttribute(attn_kernel, cudaFuncAttributeMaxDynamicSharedMemorySize, ATTN_SMEM);
        cudaStreamCreateWithFlags(&s1, cudaStreamNonBlocking);
        cudaEventCreateWithFlags(&evFork, cudaEventDisableTiming);
        cudaEventCreateWithFlags(&evJoin, cudaEventDisableTiming);
        init_done = true;
    }

    // fork immediately: kv chain on s1, q chain on stream 0
    cudaEventRecord(evFork, 0);
    cudaStreamWaitEvent(s1, evFork, 0);

    // s1: kv-weight fold+arrange, then kv GEMM
    prep_arrange_kv<<<(CDIM * CDIM / 2 + 255) / 256, 256, 0, s1>>>(kv_w, weh);
    kk<<<dim3(HW2 / 64, 1, NB * 4), 256, smem_kv, s1>>>(weh, x, (float*)kvh, nullptr, HW2);
    cudaEventRecord(evJoin, s1);

    // stream 0: q/proj weight arranges, then q GEMM
    prep_arrange_h<192, 384><<<(CQ * CDIM / 2 + 255) / 256, 256>>>(q_w, qwh, CQ);
    prep_arrange_h<192, 192><<<(CDIM * CQ / 2 + 255) / 256, 256>>>(proj_w, pwh, CDIM);
    kq<<<dim3(HW / 64, 1, NB), 256, smem_g>>>(qwh, x, (float*)qfh, nullptr, HW);

    // join: attn needs qfeat (stream 0) and kv (s1)
    cudaStreamWaitEvent(0, evJoin, 0);
    attn_kernel<<<NB * 1024, 256, ATTN_SMEM>>>();
    kp<<<dim3(HW / 64, 2, NB), 256, smem_g>>>(pwh, (const float*)fh, out, proj_b, HW);
}